// round 4
// baseline (speedup 1.0000x reference)
#include <cuda_runtime.h>
#include <cstdint>

// ---------------- problem constants ----------------
#define GRID     128      // CTAs (1 per SM, co-resident -> grid barrier safe)
#define NTHREADS 256
#define SQ       2048
#define BATCH    64
#define H        512
#define HB       (H*BATCH)   // 32768 floats per h snapshot
#define RPC      16          // gate rows per CTA (4 units x 4 gates)
#define GPLD     66          // padded ld for gate-partial smem tile (8B-aligned rows)
#define CHUNKF   16384       // staged chunk: K=256 x B=64 floats (64KB)

// ---------------- device scratch ----------------
__device__ __align__(16) float g_h1[(SQ + 1) * HB];
__device__ __align__(16) float g_h2[2 * HB];
__device__ __align__(16) float g_E2[16 * 4 * H];
__device__ int      g_pidx[SQ * BATCH];
__device__ unsigned g_isI32;
__device__ unsigned g_arrive[GRID * 32];   // 1 flag per CTA, 128B apart
__device__ unsigned g_bargen;

__device__ __forceinline__ float sigmoidf_(float x) { return 1.f / (1.f + expf(-x)); }

// Packed f32x2 FMA (Blackwell double-rate fp32 path; PTX-only).
__device__ __forceinline__ void ffma2(unsigned long long& d, unsigned long long a,
                                      unsigned long long b) {
    asm volatile("fma.rn.f32x2 %0, %1, %2, %0;" : "+l"(d) : "l"(a), "l"(b));
}
__device__ __forceinline__ unsigned long long dup2(float x) {
    unsigned long long r;
    asm volatile("mov.b64 %0, {%1, %1};" : "=l"(r) : "f"(x));
    return r;
}

// Distributed grid barrier: per-CTA release flags (no contention), CTA0
// aggregates with 128 polling threads, single release broadcast.
// target is monotonic across graph replays (base snapshot + local step).
__device__ __forceinline__ void grid_barrier(unsigned target, int cta, int tid) {
    __syncthreads();
    if (cta == 0) {
        if (tid < GRID) {
            if (tid == 0)
                asm volatile("st.release.gpu.global.u32 [%0], %1;"
                             :: "l"(&g_arrive[0]), "r"(target) : "memory");
            unsigned cur;
            do {
                asm volatile("ld.acquire.gpu.global.u32 %0, [%1];"
                             : "=r"(cur) : "l"(&g_arrive[tid * 32]) : "memory");
            } while ((int)(cur - target) < 0);
        }
        __syncthreads();
        if (tid == 0)
            asm volatile("st.release.gpu.global.u32 [%0], %1;"
                         :: "l"(&g_bargen), "r"(target) : "memory");
    } else {
        if (tid == 0) {
            asm volatile("st.release.gpu.global.u32 [%0], %1;"
                         :: "l"(&g_arrive[cta * 32]), "r"(target) : "memory");
            unsigned cur;
            do {
                asm volatile("ld.acquire.gpu.global.u32 %0, [%1];"
                             : "=r"(cur) : "l"(&g_bargen) : "memory");
            } while ((int)(cur - target) < 0);
        }
    }
    __syncthreads();
}

// ---------------- cp.async helpers ----------------
__device__ __forceinline__ void stage_chunk(float* dst, const float* __restrict__ src, int tid) {
    uint32_t s = (uint32_t)__cvta_generic_to_shared(dst) + (uint32_t)tid * 16u;
    const float4* g = reinterpret_cast<const float4*>(src) + tid;
    #pragma unroll
    for (int i = 0; i < 16; i++)
        asm volatile("cp.async.cg.shared.global [%0], [%1], 16;"
                     :: "r"(s + (uint32_t)i * (NTHREADS * 16u)), "l"(g + i * NTHREADS) : "memory");
}
#define CP_COMMIT() asm volatile("cp.async.commit_group;" ::: "memory")
#define CP_WAIT1()  asm volatile("cp.async.wait_group 1;" ::: "memory")
#define CP_WAIT0()  asm volatile("cp.async.wait_group 0;" ::: "memory")

// GEMM over one staged chunk: warp ksl takes k-slice [ksl*32, ksl*32+32) of the
// chunk; thread = 4 rows (rg*4..) x 8 batches (bo*8..) with f32x2 accumulators.
__device__ __forceinline__ void gemm_chunk(const float* __restrict__ hc,
                                           const float* __restrict__ wc,
                                           unsigned long long a2[4][4],
                                           int ksl, int rg, int bo) {
    const float* h = hc + ksl * 32 * BATCH + bo * 8;
    const float* w = wc + ksl * 32 * RPC + rg * 4;
    #pragma unroll 4
    for (int kk = 0; kk < 32; ++kk) {
        float4 w4 = *reinterpret_cast<const float4*>(w);
        ulonglong2 hA = *reinterpret_cast<const ulonglong2*>(h);      // batches +0..3
        ulonglong2 hB = *reinterpret_cast<const ulonglong2*>(h + 4);  // batches +4..7
        unsigned long long wd0 = dup2(w4.x), wd1 = dup2(w4.y);
        unsigned long long wd2 = dup2(w4.z), wd3 = dup2(w4.w);
        ffma2(a2[0][0], wd0, hA.x); ffma2(a2[0][1], wd0, hA.y);
        ffma2(a2[0][2], wd0, hB.x); ffma2(a2[0][3], wd0, hB.y);
        ffma2(a2[1][0], wd1, hA.x); ffma2(a2[1][1], wd1, hA.y);
        ffma2(a2[1][2], wd1, hB.x); ffma2(a2[1][3], wd1, hB.y);
        ffma2(a2[2][0], wd2, hA.x); ffma2(a2[2][1], wd2, hA.y);
        ffma2(a2[2][2], wd2, hB.x); ffma2(a2[2][3], wd2, hB.y);
        ffma2(a2[3][0], wd3, hA.x); ffma2(a2[3][1], wd3, hA.y);
        ffma2(a2[3][2], wd3, hB.x); ffma2(a2[3][3], wd3, hB.y);
        w += RPC; h += BATCH;
    }
}

// ---------------- setup kernels ----------------
__global__ void detect_reset() { g_isI32 = 0u; }

// int64 values in [0,4) -> odd u32 words all zero; int32 -> some nonzero.
__global__ void detect_dtype(const unsigned* __restrict__ w) {
    int i = blockIdx.x * blockDim.x + threadIdx.x;
    if (i < SQ * BATCH) {
        if ((i & 1) && w[i] != 0u) atomicOr(&g_isI32, 1u);
    }
}

__global__ void setup_misc(const void* __restrict__ inp_raw) {
    int i = blockIdx.x * blockDim.x + threadIdx.x;
    if (i < SQ * BATCH) {
        int s = i >> 6, b = i & 63;
        long long a, c;
        if (g_isI32) {
            const int* p = (const int*)inp_raw;
            a = p[b * SQ + s];
            c = p[(BATCH + b) * SQ + s];
        } else {
            const long long* p = (const long long*)inp_raw;
            a = p[(long long)b * SQ + s];
            c = p[(long long)(BATCH + b) * SQ + s];
        }
        g_pidx[s * BATCH + b] = (int)(a * 4 + c);
    }
    if (i < HB) { g_h1[i] = 0.f; g_h2[i] = 0.f; g_h2[HB + i] = 0.f; }
}

__global__ void setup_e2(const float* __restrict__ embed, const float* __restrict__ Wih) {
    int flat = blockIdx.x * blockDim.x + threadIdx.x;
    int p = flat >> 11, r = flat & 2047;
    const float* e0 = embed + (p >> 2) * H;
    const float* e1 = embed + (p & 3) * H;
    const float* w  = Wih + (size_t)r * H;
    float s = 0.f;
    #pragma unroll 4
    for (int k = 0; k < H; k++) s += (e0[k] + e1[k]) * w[k];
    g_E2[p * 2048 + r] = s;
}

// ---------------- persistent LSTM kernel ----------------
__global__ __launch_bounds__(NTHREADS, 1)
void lstm_persist(const float* __restrict__ Wih, const float* __restrict__ Whh,
                  const float* __restrict__ bih, const float* __restrict__ bhh,
                  const float* __restrict__ ln_g, const float* __restrict__ ln_b,
                  const float* __restrict__ Wp,  const float* __restrict__ bp,
                  float* __restrict__ out)
{
    extern __shared__ float sm[];
    float* ws  = sm;                       // 16384 floats (weights [k][16], <=64KB)
    float* hs  = ws + 16384;               // 2 x CHUNKF h staging buffers
    float* gp  = hs + 2 * CHUNKF;          // [8 ksl][16 r][GPLD]
    float* E2s = gp + 8 * RPC * GPLD;      // 256
    float* bs  = E2s + 256;                // 16
    __shared__ unsigned s_base;

    const int cta  = blockIdx.x;
    const int tid  = threadIdx.x;
    const int warp = tid >> 5, lane = tid & 31;
    const int ksl = warp;            // K slice 0..7
    const int rg  = lane >> 3;       // row quad
    const int bo  = lane & 7;        // batch octet
    const int uu = tid >> 6, bb = tid & 63;
    const int uglob = (cta << 2) + uu;

    if (tid == 0) {
        unsigned b_;
        asm volatile("ld.relaxed.gpu.global.u32 %0, [%1];" : "=r"(b_) : "l"(&g_bargen) : "memory");
        s_base = b_;
    }
    __syncthreads();
    unsigned gen = s_base;

    // ======== layer 0 weight/bias/E2 load ========
    for (int idx = tid; idx < RPC * H; idx += NTHREADS) {
        int r = idx >> 9, k = idx & (H - 1);
        int R = ((r >> 2) << 9) + (cta << 2) + (r & 3);
        ws[k * RPC + r] = Whh[(size_t)R * H + k];
    }
    for (int idx = tid; idx < 256; idx += NTHREADS) {
        int p = idx >> 4, r = idx & 15;
        int R = ((r >> 2) << 9) + (cta << 2) + (r & 3);
        E2s[idx] = g_E2[p * 2048 + R];
    }
    if (tid < RPC) {
        int R = ((tid >> 2) << 9) + (cta << 2) + (tid & 3);
        bs[tid] = bih[R] + bhh[R];
    }
    __syncthreads();

    float cst = 0.f;
    for (int t = 0; t < SQ; ++t) {
        const float* hbase = g_h1 + (size_t)t * HB;
        stage_chunk(hs, hbase, tid);          CP_COMMIT();
        stage_chunk(hs + CHUNKF, hbase + CHUNKF, tid); CP_COMMIT();

        unsigned long long a2[4][4];
        #pragma unroll
        for (int i = 0; i < 4; i++)
            #pragma unroll
            for (int j = 0; j < 4; j++) a2[i][j] = 0ULL;

        CP_WAIT1(); __syncthreads();
        gemm_chunk(hs, ws, a2, ksl, rg, bo);
        CP_WAIT0(); __syncthreads();
        gemm_chunk(hs + CHUNKF, ws + 256 * RPC, a2, ksl, rg, bo);

        {   // write gate partials (f32x2 pairs are consecutive batches)
            float* g0 = gp + (ksl * RPC + rg * 4) * GPLD + bo * 8;
            #pragma unroll
            for (int i = 0; i < 4; i++)
                #pragma unroll
                for (int j = 0; j < 4; j++)
                    *reinterpret_cast<unsigned long long*>(g0 + i * GPLD + 2 * j) = a2[i][j];
        }
        __syncthreads();

        int p = g_pidx[t * BATCH + bb];
        float gv[4];
        #pragma unroll
        for (int gate = 0; gate < 4; ++gate) {
            int r = (gate << 2) + uu;
            float v = bs[r] + E2s[(p << 4) + r];
            #pragma unroll
            for (int s_ = 0; s_ < 8; ++s_) v += gp[(s_ * RPC + r) * GPLD + bb];
            gv[gate] = v;
        }
        float ig = sigmoidf_(gv[0]);
        float fg = sigmoidf_(gv[1]);
        float gg = tanhf(gv[2]);
        float og = sigmoidf_(gv[3]);
        cst = fg * cst + ig * gg;
        float hv = og * tanhf(cst);
        __stcg(g_h1 + (size_t)(t + 1) * HB + uglob * BATCH + bb, hv);
        grid_barrier(++gen, cta, tid);
    }

    // ======== layer 1 weights: K=1024 (Wih2 | Whh2) ========
    {
        const float* Wih1 = Wih + (size_t)4 * H * H;
        const float* Whh1 = Whh + (size_t)4 * H * H;
        for (int idx = tid; idx < RPC * 2 * H; idx += NTHREADS) {
            int r = idx >> 10, k = idx & 1023;
            int R = ((r >> 2) << 9) + (cta << 2) + (r & 3);
            float v = (k < H) ? Wih1[(size_t)R * H + k] : Whh1[(size_t)R * H + (k - H)];
            ws[k * RPC + r] = v;
        }
        if (tid < RPC) {
            int R = ((tid >> 2) << 9) + (cta << 2) + (tid & 3);
            bs[tid] = bih[2048 + R] + bhh[2048 + R];
        }
        __syncthreads();
    }

    // prefetch x chunks for t=0 (h1 history: no recurrent dependency)
    {
        const float* x0 = g_h1 + (size_t)1 * HB;
        stage_chunk(hs, x0, tid);            CP_COMMIT();
        stage_chunk(hs + CHUNKF, x0 + CHUNKF, tid); CP_COMMIT();
    }

    cst = 0.f;
    for (int t = 0; t < SQ; ++t) {
        const float* h2src = g_h2 + (size_t)(t & 1) * HB;

        unsigned long long a2[4][4];
        #pragma unroll
        for (int i = 0; i < 4; i++)
            #pragma unroll
            for (int j = 0; j < 4; j++) a2[i][j] = 0ULL;

        // chunk0: x lo (pre-staged, DMA flew during barrier)
        CP_WAIT1(); __syncthreads();
        gemm_chunk(hs, ws, a2, ksl, rg, bo);
        __syncthreads();
        stage_chunk(hs, h2src, tid); CP_COMMIT();          // h2 lo -> buf0
        // chunk1: x hi
        CP_WAIT1(); __syncthreads();
        gemm_chunk(hs + CHUNKF, ws + 256 * RPC, a2, ksl, rg, bo);
        __syncthreads();
        stage_chunk(hs + CHUNKF, h2src + CHUNKF, tid); CP_COMMIT();  // h2 hi -> buf1
        // chunk2: h2 lo
        CP_WAIT1(); __syncthreads();
        gemm_chunk(hs, ws + 512 * RPC, a2, ksl, rg, bo);
        // chunk3: h2 hi
        CP_WAIT0(); __syncthreads();
        gemm_chunk(hs + CHUNKF, ws + 768 * RPC, a2, ksl, rg, bo);

        {
            float* g0 = gp + (ksl * RPC + rg * 4) * GPLD + bo * 8;
            #pragma unroll
            for (int i = 0; i < 4; i++)
                #pragma unroll
                for (int j = 0; j < 4; j++)
                    *reinterpret_cast<unsigned long long*>(g0 + i * GPLD + 2 * j) = a2[i][j];
        }
        __syncthreads();

        float gv[4];
        #pragma unroll
        for (int gate = 0; gate < 4; ++gate) {
            int r = (gate << 2) + uu;
            float v = bs[r];
            #pragma unroll
            for (int s_ = 0; s_ < 8; ++s_) v += gp[(s_ * RPC + r) * GPLD + bb];
            gv[gate] = v;
        }
        float ig = sigmoidf_(gv[0]);
        float fg = sigmoidf_(gv[1]);
        float gg = tanhf(gv[2]);
        float og = sigmoidf_(gv[3]);
        cst = fg * cst + ig * gg;
        float hv = og * tanhf(cst);
        __stcg(g_h2 + (size_t)((t + 1) & 1) * HB + uglob * BATCH + bb, hv);
        __syncthreads();   // all gemm reads of hs done (sync above covers), buffers free

        if (t + 1 < SQ) {  // prefetch next x chunks; DMA overlaps the barrier wait
            const float* xn = g_h1 + (size_t)(t + 2) * HB;
            stage_chunk(hs, xn, tid);            CP_COMMIT();
            stage_chunk(hs + CHUNKF, xn + CHUNKF, tid); CP_COMMIT();
        }
        grid_barrier(++gen, cta, tid);
    }

    // ======== head: LayerNorm + projection (final h2 in slot 0) ========
    if (cta < 8) {
        int b = (cta << 3) + warp;
        const float* h2 = g_h2;
        float s1 = 0.f, s2 = 0.f;
        for (int u = lane; u < H; u += 32) {
            float v = __ldcg(h2 + u * BATCH + b);
            s1 += v; s2 += v * v;
        }
        #pragma unroll
        for (int o = 16; o; o >>= 1) {
            s1 += __shfl_xor_sync(0xFFFFFFFFu, s1, o);
            s2 += __shfl_xor_sync(0xFFFFFFFFu, s2, o);
        }
        float mu  = s1 * (1.f / H);
        float var = s2 * (1.f / H) - mu * mu;
        float rs  = rsqrtf(var + 1e-5f);
        float acc = 0.f;
        for (int u = lane; u < H; u += 32) {
            float v  = __ldcg(h2 + u * BATCH + b);
            float hn = (v - mu) * rs * ln_g[u] + ln_b[u];
            acc += hn * Wp[u];
        }
        #pragma unroll
        for (int o = 16; o; o >>= 1) acc += __shfl_xor_sync(0xFFFFFFFFu, acc, o);
        if (lane == 0) out[b] = acc + bp[0];
    }
}

// ---------------- launch ----------------
extern "C" void kernel_launch(void* const* d_in, const int* in_sizes, int n_in,
                              void* d_out, int out_size) {
    const void*  inp   = d_in[0];
    const float* embed = (const float*)d_in[1];
    const float* Wih   = (const float*)d_in[2];
    const float* Whh   = (const float*)d_in[3];
    const float* bih   = (const float*)d_in[4];
    const float* bhh   = (const float*)d_in[5];
    const float* ln_g  = (const float*)d_in[6];
    const float* ln_b  = (const float*)d_in[7];
    const float* Wp    = (const float*)d_in[8];
    const float* bp    = (const float*)d_in[9];
    float* out = (float*)d_out;

    detect_reset<<<1, 1>>>();
    detect_dtype<<<512, 256>>>((const unsigned*)inp);
    setup_misc<<<512, 256>>>(inp);
    setup_e2<<<128, 256>>>(embed, Wih);

    int smem = (16384 + 2 * CHUNKF + 8 * RPC * GPLD + 256 + 16) * 4;  // 231,488 B
    cudaFuncSetAttribute(lstm_persist, cudaFuncAttributeMaxDynamicSharedMemorySize, smem);
    lstm_persist<<<GRID, NTHREADS, smem>>>(Wih, Whh, bih, bhh, ln_g, ln_b, Wp, bp, out);
}

// round 5
// speedup vs baseline: 1.6695x; 1.6695x over previous
#include <cuda_runtime.h>
#include <cuda_bf16.h>
#include <cstdint>

// ---------------- problem constants ----------------
#define GRID     128
#define NTHREADS 256
#define SQ       2048
#define BATCH    64
#define H        512
#define HB       (H*BATCH)     // 32768 elements per h snapshot
#define GPLD     68            // padded ld for gate smem tile

// smem byte offsets
#define SMEM_SB0  0            // staging buf 0: [hi 32KB][lo 32KB]
#define SMEM_SB1  65536
#define SMEM_WS   131072       // weights: [hi 32KB][lo 32KB] (1024 rows x 32B)
#define SMEM_GP   196608       // 16 x GPLD x f32 = 4352B
#define SMEM_E2S  200960       // 16 pairs x 16 rows f32 = 1KB
#define SMEM_BS   201984       // 16 f32
#define SMEM_TOT  202112

// ---------------- device scratch ----------------
__device__ __align__(16) __nv_bfloat16 g_h1h[(SQ + 1) * HB];
__device__ __align__(16) __nv_bfloat16 g_h1l[(SQ + 1) * HB];
__device__ __align__(16) __nv_bfloat16 g_h2h[2 * HB];
__device__ __align__(16) __nv_bfloat16 g_h2l[2 * HB];
__device__ __align__(16) float g_E2[16 * 4 * H];
__device__ int      g_pidx[SQ * BATCH];
__device__ unsigned g_isI32;
__device__ unsigned g_barcnt;
__device__ unsigned g_bargen;

__device__ __forceinline__ float sigmoidf_(float x) { return 1.f / (1.f + expf(-x)); }

// swizzled element index within one h snapshot: unit u row (128B), XOR-swizzled
// 16B groups so ldmatrix column reads are conflict-free.
__device__ __forceinline__ int hswz(int u, int b) {
    return u * 64 + ((((b >> 3) ^ (u & 7))) << 3) + (b & 7);
}

// ---------------- PTX helpers ----------------
__device__ __forceinline__ void ldmx4t(unsigned* r, uint32_t a) {
    asm volatile("ldmatrix.sync.aligned.m8n8.x4.trans.shared.b16 {%0,%1,%2,%3},[%4];"
                 : "=r"(r[0]), "=r"(r[1]), "=r"(r[2]), "=r"(r[3]) : "r"(a));
}
__device__ __forceinline__ void ldmx2t(unsigned* r, uint32_t a) {
    asm volatile("ldmatrix.sync.aligned.m8n8.x2.trans.shared.b16 {%0,%1},[%2];"
                 : "=r"(r[0]), "=r"(r[1]) : "r"(a));
}
__device__ __forceinline__ void mma16816(float* d, const unsigned* a, const unsigned* b) {
    asm volatile("mma.sync.aligned.m16n8k16.row.col.f32.bf16.bf16.f32 "
                 "{%0,%1,%2,%3},{%4,%5,%6,%7},{%8,%9},{%0,%1,%2,%3};"
                 : "+f"(d[0]), "+f"(d[1]), "+f"(d[2]), "+f"(d[3])
                 : "r"(a[0]), "r"(a[1]), "r"(a[2]), "r"(a[3]), "r"(b[0]), "r"(b[1]));
}
__device__ __forceinline__ void stg_bf16(__nv_bfloat16* p, __nv_bfloat16 v) {
    unsigned short u = *reinterpret_cast<unsigned short*>(&v);
    asm volatile("st.global.cg.u16 [%0], %1;" :: "l"(p), "h"(u) : "memory");
}
__device__ __forceinline__ float ldg_bf16(const __nv_bfloat16* p) {
    unsigned short u;
    asm volatile("ld.global.cg.u16 %0,[%1];" : "=h"(u) : "l"(p));
    __nv_bfloat16 b = *reinterpret_cast<__nv_bfloat16*>(&u);
    return __bfloat162float(b);
}

// Fence-free centralized grid barrier (proven in R3).
__device__ __forceinline__ void grid_barrier(unsigned target) {
    __syncthreads();
    if (threadIdx.x == 0) {
        unsigned prev;
        asm volatile("atom.release.gpu.global.add.u32 %0,[%1],%2;"
                     : "=r"(prev) : "l"(&g_barcnt), "r"(1u) : "memory");
        if (prev == GRID - 1u) {
            asm volatile("st.relaxed.gpu.global.u32 [%0],%1;" :: "l"(&g_barcnt), "r"(0u) : "memory");
            asm volatile("st.release.gpu.global.u32 [%0],%1;" :: "l"(&g_bargen), "r"(target) : "memory");
        } else {
            unsigned cur;
            do {
                asm volatile("ld.acquire.gpu.global.u32 %0,[%1];" : "=r"(cur) : "l"(&g_bargen) : "memory");
            } while ((int)(cur - target) < 0);
        }
    }
    __syncthreads();
}

// stage one K=256 chunk (hi 32KB + lo 32KB) into a staging buffer
__device__ __forceinline__ void stageC(uint32_t sdst, const __nv_bfloat16* gh,
                                       const __nv_bfloat16* gl, int tid) {
    uint32_t s = sdst + (uint32_t)tid * 16u;
    const char* a = (const char*)gh + tid * 16;
    const char* b = (const char*)gl + tid * 16;
    #pragma unroll
    for (int i = 0; i < 8; i++) {
        asm volatile("cp.async.cg.shared.global [%0],[%1],16;"
                     :: "r"(s + (uint32_t)i * 4096u), "l"(a + i * 4096) : "memory");
        asm volatile("cp.async.cg.shared.global [%0],[%1],16;"
                     :: "r"(s + 32768u + (uint32_t)i * 4096u), "l"(b + i * 4096) : "memory");
    }
}
#define CP_COMMIT() asm volatile("cp.async.commit_group;" ::: "memory")
#define CP_WAIT1()  asm volatile("cp.async.wait_group 1;" ::: "memory")
#define CP_WAIT0()  asm volatile("cp.async.wait_group 0;" ::: "memory")

// MMA over one staged chunk (K=256 = 16 k16-tiles). 3 bf16 MMAs per tile
// (hi*hi + hi*lo + lo*hi) accumulate into d[4] (fp32).
__device__ __forceinline__ void mma_chunk(uint32_t bufu, uint32_t bB, float* d,
                                          uint32_t aoff) {
    uint32_t a = bufu + aoff;
    #pragma unroll
    for (int tile = 0; tile < 16; ++tile) {
        unsigned Ah[4], Al[4], Bh[2], Bl[2];
        ldmx4t(Ah, a);
        ldmx4t(Al, a + 32768u);
        ldmx2t(Bh, bB);
        ldmx2t(Bl, bB + 32768u);
        mma16816(d, Ah, Bh);
        mma16816(d, Ah, Bl);
        mma16816(d, Al, Bh);
        a  += 2048u;   // 16 k-rows * 128B
        bB += 512u;    // 16 k-rows * 32B
    }
}

// ---------------- setup kernels ----------------
__global__ void detect_reset() { g_isI32 = 0u; }

// int64 values in [0,4) -> odd u32 words all zero; int32 -> some nonzero.
__global__ void detect_dtype(const unsigned* __restrict__ w) {
    int i = blockIdx.x * blockDim.x + threadIdx.x;
    if (i < SQ * BATCH) {
        if ((i & 1) && w[i] != 0u) atomicOr(&g_isI32, 1u);
    }
}

__global__ void setup_misc(const void* __restrict__ inp_raw) {
    int i = blockIdx.x * blockDim.x + threadIdx.x;   // 131072 threads
    if (i < SQ * BATCH) {
        int s = i >> 6, b = i & 63;
        long long a, c;
        if (g_isI32) {
            const int* p = (const int*)inp_raw;
            a = p[b * SQ + s];
            c = p[(BATCH + b) * SQ + s];
        } else {
            const long long* p = (const long long*)inp_raw;
            a = p[(long long)b * SQ + s];
            c = p[(long long)(BATCH + b) * SQ + s];
        }
        g_pidx[s * BATCH + b] = (int)(a * 4 + c);
    }
    __nv_bfloat16 z = __float2bfloat16(0.f);
    if (i < HB) { g_h1h[i] = z; g_h1l[i] = z; }
    if (i < 2 * HB) { g_h2h[i] = z; g_h2l[i] = z; }
}

__global__ void setup_e2(const float* __restrict__ embed, const float* __restrict__ Wih) {
    int flat = blockIdx.x * blockDim.x + threadIdx.x;
    int p = flat >> 11, r = flat & 2047;
    const float* e0 = embed + (p >> 2) * H;
    const float* e1 = embed + (p & 3) * H;
    const float* w  = Wih + (size_t)r * H;
    float s = 0.f;
    #pragma unroll 4
    for (int k = 0; k < H; k++) s += (e0[k] + e1[k]) * w[k];
    g_E2[p * 2048 + r] = s;
}

// ---------------- persistent LSTM kernel ----------------
// CTA owns 16 gate rows (4 hidden units x 4 gates). Warp = (bm = warp>>1 batch
// m16-tile, rn = warp&1 row n8-tile); each warp covers all K -> no reduction.
__global__ __launch_bounds__(NTHREADS, 1)
void lstm_persist(const float* __restrict__ Wih, const float* __restrict__ Whh,
                  const float* __restrict__ bih, const float* __restrict__ bhh,
                  const float* __restrict__ ln_g, const float* __restrict__ ln_b,
                  const float* __restrict__ Wp,  const float* __restrict__ bp,
                  float* __restrict__ out)
{
    extern __shared__ char smem[];
    __nv_bfloat16* wsh = (__nv_bfloat16*)(smem + SMEM_WS);
    __nv_bfloat16* wsl = (__nv_bfloat16*)(smem + SMEM_WS + 32768);
    float* gp  = (float*)(smem + SMEM_GP);
    float* E2s = (float*)(smem + SMEM_E2S);
    float* bs  = (float*)(smem + SMEM_BS);
    uint32_t su = (uint32_t)__cvta_generic_to_shared(smem);
    const uint32_t SB0 = su + SMEM_SB0, SB1 = su + SMEM_SB1, WSu = su + SMEM_WS;
    __shared__ unsigned s_base;

    const int cta  = blockIdx.x;
    const int tid  = threadIdx.x;
    const int warp = tid >> 5, lane = tid & 31;
    const int bm = warp >> 1;           // batch tile (16 batches)
    const int rn = warp & 1;            // row tile (8 rows)
    const int uu = tid >> 6, bb = tid & 63;   // eltwise mapping
    const int uglob = (cta << 2) + uu;

    // per-lane ldmatrix address offsets
    const int kA  = (lane & 7) + ((lane & 16) >> 1);
    const int jbA = bm * 2 + ((lane >> 3) & 1);
    const uint32_t aoff = (uint32_t)(kA * 128 + ((jbA ^ (kA & 7)) << 4));
    const int kB  = lane & 15;
    const uint32_t bB0 = WSu + (uint32_t)(kB * 32 + ((rn ^ ((kB >> 2) & 1)) << 4));

    // D-fragment -> gp mapping
    const int dr = rn * 8 + ((lane & 3) << 1);
    const int dc = bm * 16 + (lane >> 2);

    if (tid == 0) {
        unsigned b_;
        asm volatile("ld.relaxed.gpu.global.u32 %0,[%1];" : "=r"(b_) : "l"(&g_bargen) : "memory");
        s_base = b_;
    }
    __syncthreads();
    unsigned gen = s_base;

    // ======== layer 0: convert Whh slice to bf16 hi/lo smem; E2, bias ========
    for (int idx = tid; idx < 16 * H; idx += NTHREADS) {
        int k = idx >> 4, r = idx & 15;
        int R = ((r >> 2) << 9) + (cta << 2) + (r & 3);
        float w = Whh[(size_t)R * H + k];
        __nv_bfloat16 hi = __float2bfloat16(w);
        float rem = w - __bfloat162float(hi);
        __nv_bfloat16 lo = __float2bfloat16(rem);
        int e = k * 16 + (((r >> 3) ^ ((k >> 2) & 1)) << 3) + (r & 7);
        wsh[e] = hi; wsl[e] = lo;
    }
    for (int idx = tid; idx < 256; idx += NTHREADS) {
        int p = idx >> 4, r = idx & 15;
        int R = ((r >> 2) << 9) + (cta << 2) + (r & 3);
        E2s[idx] = g_E2[p * 2048 + R];
    }
    if (tid < 16) {
        int R = ((tid >> 2) << 9) + (cta << 2) + (tid & 3);
        bs[tid] = bih[R] + bhh[R];
    }
    __syncthreads();

    float cst = 0.f;
    for (int t = 0; t < SQ; ++t) {
        const __nv_bfloat16* gh = g_h1h + (size_t)t * HB;
        const __nv_bfloat16* gl = g_h1l + (size_t)t * HB;
        stageC(SB0, gh, gl, tid);                 CP_COMMIT();
        stageC(SB1, gh + 16384, gl + 16384, tid); CP_COMMIT();

        float d[4] = {0.f, 0.f, 0.f, 0.f};
        CP_WAIT1(); __syncthreads();
        mma_chunk(SB0, bB0, d, aoff);
        CP_WAIT0(); __syncthreads();
        mma_chunk(SB1, bB0 + 256u * 32u, d, aoff);

        gp[dr * GPLD + dc]           = d[0];
        gp[(dr + 1) * GPLD + dc]     = d[1];
        gp[dr * GPLD + dc + 8]       = d[2];
        gp[(dr + 1) * GPLD + dc + 8] = d[3];
        __syncthreads();

        int p = g_pidx[t * BATCH + bb];
        float gv[4];
        #pragma unroll
        for (int gate = 0; gate < 4; ++gate) {
            int r = (gate << 2) + uu;
            gv[gate] = bs[r] + E2s[(p << 4) + r] + gp[r * GPLD + bb];
        }
        float ig = sigmoidf_(gv[0]);
        float fg = sigmoidf_(gv[1]);
        float gg = tanhf(gv[2]);
        float og = sigmoidf_(gv[3]);
        cst = fg * cst + ig * gg;
        float hv = og * tanhf(cst);
        {
            __nv_bfloat16 hi = __float2bfloat16(hv);
            float rem = hv - __bfloat162float(hi);
            __nv_bfloat16 lo = __float2bfloat16(rem);
            size_t off = (size_t)(t + 1) * HB + hswz(uglob, bb);
            stg_bf16(g_h1h + off, hi);
            stg_bf16(g_h1l + off, lo);
        }
        grid_barrier(++gen);
    }

    // ======== layer 1 weights: K=1024 (Wih2 rows 0-511 | Whh2 rows 512-1023) ========
    {
        const float* Wih1 = Wih + (size_t)4 * H * H;
        const float* Whh1 = Whh + (size_t)4 * H * H;
        for (int idx = tid; idx < 16 * 2 * H; idx += NTHREADS) {
            int k = idx >> 4, r = idx & 15;
            int R = ((r >> 2) << 9) + (cta << 2) + (r & 3);
            float w = (k < H) ? Wih1[(size_t)R * H + k] : Whh1[(size_t)R * H + (k - H)];
            __nv_bfloat16 hi = __float2bfloat16(w);
            float rem = w - __bfloat162float(hi);
            __nv_bfloat16 lo = __float2bfloat16(rem);
            int e = k * 16 + (((r >> 3) ^ ((k >> 2) & 1)) << 3) + (r & 7);
            wsh[e] = hi; wsl[e] = lo;
        }
        if (tid < 16) {
            int R = ((tid >> 2) << 9) + (cta << 2) + (tid & 3);
            bs[tid] = bih[2048 + R] + bhh[2048 + R];
        }
        __syncthreads();
    }

    // prefetch x chunks for t=0 (x = h1 snapshot 1; no recurrent dependency)
    {
        const __nv_bfloat16* xh = g_h1h + (size_t)1 * HB;
        const __nv_bfloat16* xl = g_h1l + (size_t)1 * HB;
        stageC(SB0, xh, xl, tid);                 CP_COMMIT();
        stageC(SB1, xh + 16384, xl + 16384, tid); CP_COMMIT();
    }

    cst = 0.f;
    for (int t = 0; t < SQ; ++t) {
        const __nv_bfloat16* h2h = g_h2h + (size_t)(t & 1) * HB;
        const __nv_bfloat16* h2l = g_h2l + (size_t)(t & 1) * HB;

        float d[4] = {0.f, 0.f, 0.f, 0.f};
        // x lo-half (pre-staged; DMA flew during barrier wait)
        CP_WAIT1(); __syncthreads();
        mma_chunk(SB0, bB0, d, aoff);
        __syncthreads();
        stageC(SB0, h2h, h2l, tid); CP_COMMIT();
        // x hi-half
        CP_WAIT1(); __syncthreads();
        mma_chunk(SB1, bB0 + 256u * 32u, d, aoff);
        __syncthreads();
        stageC(SB1, h2h + 16384, h2l + 16384, tid); CP_COMMIT();
        // h2 lo-half
        CP_WAIT1(); __syncthreads();
        mma_chunk(SB0, bB0 + 512u * 32u, d, aoff);
        // h2 hi-half
        CP_WAIT0(); __syncthreads();
        mma_chunk(SB1, bB0 + 768u * 32u, d, aoff);

        gp[dr * GPLD + dc]           = d[0];
        gp[(dr + 1) * GPLD + dc]     = d[1];
        gp[dr * GPLD + dc + 8]       = d[2];
        gp[(dr + 1) * GPLD + dc + 8] = d[3];
        __syncthreads();

        float gv[4];
        #pragma unroll
        for (int gate = 0; gate < 4; ++gate) {
            int r = (gate << 2) + uu;
            gv[gate] = bs[r] + gp[r * GPLD + bb];
        }
        float ig = sigmoidf_(gv[0]);
        float fg = sigmoidf_(gv[1]);
        float gg = tanhf(gv[2]);
        float og = sigmoidf_(gv[3]);
        cst = fg * cst + ig * gg;
        float hv = og * tanhf(cst);
        {
            __nv_bfloat16 hi = __float2bfloat16(hv);
            float rem = hv - __bfloat162float(hi);
            __nv_bfloat16 lo = __float2bfloat16(rem);
            size_t off = (size_t)((t + 1) & 1) * HB + hswz(uglob, bb);
            stg_bf16(g_h2h + off, hi);
            stg_bf16(g_h2l + off, lo);
        }
        __syncthreads();   // all warps past mma reads; staging buffers reusable

        if (t + 1 < SQ) {  // prefetch next x; DMA overlaps the barrier wait
            const __nv_bfloat16* xh = g_h1h + (size_t)(t + 2) * HB;
            const __nv_bfloat16* xl = g_h1l + (size_t)(t + 2) * HB;
            stageC(SB0, xh, xl, tid);                 CP_COMMIT();
            stageC(SB1, xh + 16384, xl + 16384, tid); CP_COMMIT();
        }
        grid_barrier(++gen);
    }

    // ======== head: LayerNorm + projection (final h2 in slot 0) ========
    if (cta < 8) {
        int b = (cta << 3) + warp;
        float s1 = 0.f, s2 = 0.f;
        for (int u = lane; u < H; u += 32) {
            int off = hswz(u, b);
            float v = ldg_bf16(g_h2h + off) + ldg_bf16(g_h2l + off);
            s1 += v; s2 += v * v;
        }
        #pragma unroll
        for (int o = 16; o; o >>= 1) {
            s1 += __shfl_xor_sync(0xFFFFFFFFu, s1, o);
            s2 += __shfl_xor_sync(0xFFFFFFFFu, s2, o);
        }
        float mu  = s1 * (1.f / H);
        float var = s2 * (1.f / H) - mu * mu;
        float rs  = rsqrtf(var + 1e-5f);
        float acc = 0.f;
        for (int u = lane; u < H; u += 32) {
            int off = hswz(u, b);
            float v  = ldg_bf16(g_h2h + off) + ldg_bf16(g_h2l + off);
            float hn = (v - mu) * rs * ln_g[u] + ln_b[u];
            acc += hn * Wp[u];
        }
        #pragma unroll
        for (int o = 16; o; o >>= 1) acc += __shfl_xor_sync(0xFFFFFFFFu, acc, o);
        if (lane == 0) out[b] = acc + bp[0];
    }
}

// ---------------- launch ----------------
extern "C" void kernel_launch(void* const* d_in, const int* in_sizes, int n_in,
                              void* d_out, int out_size) {
    const void*  inp   = d_in[0];
    const float* embed = (const float*)d_in[1];
    const float* Wih   = (const float*)d_in[2];
    const float* Whh   = (const float*)d_in[3];
    const float* bih   = (const float*)d_in[4];
    const float* bhh   = (const float*)d_in[5];
    const float* ln_g  = (const float*)d_in[6];
    const float* ln_b  = (const float*)d_in[7];
    const float* Wp    = (const float*)d_in[8];
    const float* bp    = (const float*)d_in[9];
    float* out = (float*)d_out;

    detect_reset<<<1, 1>>>();
    detect_dtype<<<512, 256>>>((const unsigned*)inp);
    setup_misc<<<512, 256>>>(inp);
    setup_e2<<<128, 256>>>(embed, Wih);

    cudaFuncSetAttribute(lstm_persist, cudaFuncAttributeMaxDynamicSharedMemorySize, SMEM_TOT);
    lstm_persist<<<GRID, NTHREADS, SMEM_TOT>>>(Wih, Whh, bih, bhh, ln_g, ln_b, Wp, bp, out);
}

// round 6
// speedup vs baseline: 1.9459x; 1.1655x over previous
#include <cuda_runtime.h>
#include <cuda_bf16.h>
#include <cstdint>

// ---------------- problem constants ----------------
#define GRID     128
#define NTHREADS 256
#define SQ       2048
#define H        512
#define HBH      16384     // elements per (t, half) = 512k x 32b
#define GPLD     36

// smem byte offsets
#define SMEM_SB0 0         // staging buf 0: 32KB (hi 16KB | lo 16KB), K=256 chunk
#define SMEM_SB1 32768
#define SMEM_WS  65536     // weights: hi 64KB | lo 64KB  (32 rows x K<=1024)
#define SMEM_GP  196608    // 32 x GPLD x f32
#define SMEM_E2S 201216    // 16 pairs x 32 rows f32
#define SMEM_BS  203264    // 32 f32
#define SMEM_TOT 203392

// ---------------- device scratch ----------------
__device__ __align__(16) __nv_bfloat16 g_h1h[(SQ + 1) * 2 * HBH];
__device__ __align__(16) __nv_bfloat16 g_h1l[(SQ + 1) * 2 * HBH];
__device__ __align__(16) __nv_bfloat16 g_h2h[2 * 2 * HBH];
__device__ __align__(16) __nv_bfloat16 g_h2l[2 * 2 * HBH];
__device__ __align__(16) float g_E2[16 * 4 * H];
__device__ int      g_pidx[SQ * 64];
__device__ unsigned g_isI32;
__device__ unsigned g_c1[2 * 8 * 32];   // group counters (128B apart)
__device__ unsigned g_c2[2 * 32];       // root counters
__device__ unsigned g_gen[2 * 32];      // per-half generation

__device__ __forceinline__ float sigmoidf_(float x) { return 1.f / (1.f + expf(-x)); }

// element offset inside one (t, half) plane for value (k=unit, b=local batch)
// paired-k rows of 128B, XOR swizzle -> conflict-free ldmatrix
__device__ __forceinline__ int eoff_h(int k, int b) {
    return (k >> 1) * 64 + (k & 1) * 32 + ((((b >> 3) ^ ((k >> 1) & 3))) << 3) + (b & 7);
}

// ---------------- PTX helpers ----------------
__device__ __forceinline__ void ldmx4t(unsigned* r, uint32_t a) {
    asm volatile("ldmatrix.sync.aligned.m8n8.x4.trans.shared.b16 {%0,%1,%2,%3},[%4];"
                 : "=r"(r[0]), "=r"(r[1]), "=r"(r[2]), "=r"(r[3]) : "r"(a));
}
__device__ __forceinline__ void ldmx2t(unsigned* r, uint32_t a) {
    asm volatile("ldmatrix.sync.aligned.m8n8.x2.trans.shared.b16 {%0,%1},[%2];"
                 : "=r"(r[0]), "=r"(r[1]) : "r"(a));
}
__device__ __forceinline__ void mma16816(float* d, const unsigned* a, const unsigned* b) {
    asm volatile("mma.sync.aligned.m16n8k16.row.col.f32.bf16.bf16.f32 "
                 "{%0,%1,%2,%3},{%4,%5,%6,%7},{%8,%9},{%0,%1,%2,%3};"
                 : "+f"(d[0]), "+f"(d[1]), "+f"(d[2]), "+f"(d[3])
                 : "r"(a[0]), "r"(a[1]), "r"(a[2]), "r"(a[3]), "r"(b[0]), "r"(b[1]));
}
__device__ __forceinline__ void stg_bf16(__nv_bfloat16* p, __nv_bfloat16 v) {
    unsigned short u = *reinterpret_cast<unsigned short*>(&v);
    asm volatile("st.global.cg.u16 [%0], %1;" :: "l"(p), "h"(u) : "memory");
}
__device__ __forceinline__ float ldg_bf16(const __nv_bfloat16* p) {
    unsigned short u;
    asm volatile("ld.global.cg.u16 %0,[%1];" : "=h"(u) : "l"(p));
    __nv_bfloat16 b = *reinterpret_cast<__nv_bfloat16*>(&u);
    return __bfloat162float(b);
}

// Hierarchical per-half barrier: 8 groups of 8 arrivals, then root of 8,
// then release broadcast. Counters return to 0 (replay-safe); gen monotonic.
__device__ __forceinline__ void half_barrier(unsigned target, int half, int grp) {
    __syncthreads();
    if (threadIdx.x == 0) {
        unsigned* c1 = &g_c1[(half * 8 + grp) * 32];
        unsigned* c2 = &g_c2[half * 32];
        unsigned* gv = &g_gen[half * 32];
        unsigned p1;
        asm volatile("atom.acq_rel.gpu.global.add.u32 %0,[%1],%2;"
                     : "=r"(p1) : "l"(c1), "r"(1u) : "memory");
        bool done = false;
        if (p1 == 7u) {
            asm volatile("st.relaxed.gpu.global.u32 [%0],%1;" :: "l"(c1), "r"(0u) : "memory");
            unsigned p2;
            asm volatile("atom.acq_rel.gpu.global.add.u32 %0,[%1],%2;"
                         : "=r"(p2) : "l"(c2), "r"(1u) : "memory");
            if (p2 == 7u) {
                asm volatile("st.relaxed.gpu.global.u32 [%0],%1;" :: "l"(c2), "r"(0u) : "memory");
                asm volatile("st.release.gpu.global.u32 [%0],%1;" :: "l"(gv), "r"(target) : "memory");
                done = true;
            }
        }
        if (!done) {
            unsigned cur;
            do {
                asm volatile("ld.acquire.gpu.global.u32 %0,[%1];" : "=r"(cur) : "l"(gv) : "memory");
            } while ((int)(cur - target) < 0);
        }
    }
    __syncthreads();
}

// stage one 32KB chunk (hi 16KB + lo 16KB) into a staging buffer
__device__ __forceinline__ void stageC(uint32_t sdst, const __nv_bfloat16* gh,
                                       const __nv_bfloat16* gl, int tid) {
    uint32_t s = sdst + (uint32_t)tid * 16u;
    const char* a = (const char*)gh + tid * 16;
    const char* b = (const char*)gl + tid * 16;
    #pragma unroll
    for (int i = 0; i < 4; i++) {
        asm volatile("cp.async.cg.shared.global [%0],[%1],16;"
                     :: "r"(s + (uint32_t)i * 4096u), "l"(a + i * 4096) : "memory");
        asm volatile("cp.async.cg.shared.global [%0],[%1],16;"
                     :: "r"(s + 16384u + (uint32_t)i * 4096u), "l"(b + i * 4096) : "memory");
    }
}
#define CP_COMMIT() asm volatile("cp.async.commit_group;" ::: "memory")
#define CP_WAIT1()  asm volatile("cp.async.wait_group 1;" ::: "memory")
#define CP_WAIT0()  asm volatile("cp.async.wait_group 0;" ::: "memory")

// MMA over one K=256 chunk (16 k16-tiles); 3 bf16 MMAs/tile (hi*hi+hi*lo+lo*hi)
__device__ __forceinline__ void mma_chunk(uint32_t abuf, uint32_t bw, float* d, uint32_t aoff) {
    uint32_t a = abuf + aoff;
    #pragma unroll
    for (int tile = 0; tile < 16; ++tile) {
        unsigned Ah[4], Al[4], Bh[2], Bl[2];
        ldmx4t(Ah, a);
        ldmx4t(Al, a + 16384u);
        ldmx2t(Bh, bw);
        ldmx2t(Bl, bw + 65536u);
        mma16816(d, Ah, Bh);
        mma16816(d, Ah, Bl);
        mma16816(d, Al, Bh);
        a  += 1024u;
        bw += 1024u;
    }
}

// ---------------- setup kernels ----------------
__global__ void detect_reset() { g_isI32 = 0u; }

// int64 values in [0,4) -> odd u32 words all zero; int32 -> some nonzero.
__global__ void detect_dtype(const unsigned* __restrict__ w) {
    int i = blockIdx.x * blockDim.x + threadIdx.x;
    if (i < SQ * 64) {
        if ((i & 1) && w[i] != 0u) atomicOr(&g_isI32, 1u);
    }
}

__global__ void setup_misc(const void* __restrict__ inp_raw) {
    int i = blockIdx.x * blockDim.x + threadIdx.x;   // 131072 threads
    if (i < SQ * 64) {
        int s = i >> 6, b = i & 63;
        long long a, c;
        if (g_isI32) {
            const int* p = (const int*)inp_raw;
            a = p[b * SQ + s];
            c = p[(64 + b) * SQ + s];
        } else {
            const long long* p = (const long long*)inp_raw;
            a = p[(long long)b * SQ + s];
            c = p[(long long)(64 + b) * SQ + s];
        }
        g_pidx[s * 64 + b] = (int)(a * 4 + c);
    }
    __nv_bfloat16 z = __float2bfloat16(0.f);
    if (i < 2 * HBH) { g_h1h[i] = z; g_h1l[i] = z; }          // t=0, both halves
    if (i < 4 * HBH) { g_h2h[i] = z; g_h2l[i] = z; }          // both slots/halves
}

__global__ void setup_e2(const float* __restrict__ embed, const float* __restrict__ Wih) {
    int flat = blockIdx.x * blockDim.x + threadIdx.x;
    int p = flat >> 11, r = flat & 2047;
    const float* e0 = embed + (p >> 2) * H;
    const float* e1 = embed + (p & 3) * H;
    const float* w  = Wih + (size_t)r * H;
    float s = 0.f;
    #pragma unroll 4
    for (int k = 0; k < H; k++) s += (e0[k] + e1[k]) * w[k];
    g_E2[p * 2048 + r] = s;
}

// ---------------- persistent LSTM kernel ----------------
// CTA = (unit-group ug = cta>>1, batch-half bh = cta&1). Owns 8 units
// (32 gate rows) x 32 batches. Warp = (rn = warp>>1 row n8-tile 0..3,
// bm = warp&1 batch m16-tile 0..1); each warp covers all K (no reduction).
__global__ __launch_bounds__(NTHREADS, 1)
void lstm_persist(const float* __restrict__ Wih, const float* __restrict__ Whh,
                  const float* __restrict__ bih, const float* __restrict__ bhh,
                  const float* __restrict__ ln_g, const float* __restrict__ ln_b,
                  const float* __restrict__ Wp,  const float* __restrict__ bp,
                  float* __restrict__ out)
{
    extern __shared__ char smem[];
    __nv_bfloat16* wsh = (__nv_bfloat16*)(smem + SMEM_WS);
    __nv_bfloat16* wsl = (__nv_bfloat16*)(smem + SMEM_WS + 65536);
    float* gp  = (float*)(smem + SMEM_GP);
    float* E2s = (float*)(smem + SMEM_E2S);
    float* bs  = (float*)(smem + SMEM_BS);
    uint32_t su = (uint32_t)__cvta_generic_to_shared(smem);
    const uint32_t SB0u = su + SMEM_SB0, SB1u = su + SMEM_SB1, WSu = su + SMEM_WS;
    __shared__ unsigned s_base;

    const int cta  = blockIdx.x;
    const int tid  = threadIdx.x;
    const int warp = tid >> 5, lane = tid & 31;
    const int ug   = cta >> 1;          // unit group 0..63
    const int bh   = cta & 1;           // batch half
    const int grp  = ug >> 3;           // barrier group 0..7
    const int rn = warp >> 1;           // row n8-tile 0..3
    const int bm = warp & 1;            // batch m16-tile 0..1
    const int uu = tid >> 5, bl_e = tid & 31;   // eltwise: unit 0..7, local batch

    // per-lane ldmatrix offsets (paired-k XOR-swizzled layout)
    const int kA  = (lane & 7) + ((lane & 16) >> 1);
    const int jbA = bm * 2 + ((lane >> 3) & 1);
    const uint32_t aoff = (uint32_t)((kA >> 1) * 128 + (kA & 1) * 64 +
                                     ((jbA ^ ((kA >> 1) & 3)) << 4));
    const int kB  = lane & 15;
    const uint32_t bOff = (uint32_t)((kB >> 1) * 128 + (kB & 1) * 64 +
                                     ((rn ^ ((kB >> 1) & 3)) << 4));

    // D-fragment -> gp mapping (m=batch, n=gate-row)
    const int dr = rn * 8 + ((lane & 3) << 1);
    const int dc = bm * 16 + (lane >> 2);

    if (tid == 0) {
        unsigned b_;
        asm volatile("ld.relaxed.gpu.global.u32 %0,[%1];" : "=r"(b_) : "l"(&g_gen[bh * 32]) : "memory");
        s_base = b_;
    }
    __syncthreads();
    unsigned gen = s_base;

    // ======== layer 0: Whh slice -> bf16 hi/lo smem; E2; bias ========
    for (int idx = tid; idx < 32 * H; idx += NTHREADS) {
        int r = idx >> 9, k = idx & (H - 1);
        int R = ((r >> 3) << 9) + (ug << 3) + (r & 7);
        float w = Whh[(size_t)R * H + k];
        __nv_bfloat16 hi = __float2bfloat16(w);
        float rem = w - __bfloat162float(hi);
        __nv_bfloat16 lo = __float2bfloat16(rem);
        int e = eoff_h(k, 0) - (0) ;  // base of k-row
        e = (k >> 1) * 64 + (k & 1) * 32 + ((((r >> 3) ^ ((k >> 1) & 3))) << 3) + (r & 7);
        wsh[e] = hi; wsl[e] = lo;
    }
    for (int idx = tid; idx < 512; idx += NTHREADS) {
        int p = idx >> 5, r = idx & 31;
        int R = ((r >> 3) << 9) + (ug << 3) + (r & 7);
        E2s[idx] = g_E2[p * 2048 + R];
    }
    if (tid < 32) {
        int R = ((tid >> 3) << 9) + (ug << 3) + (tid & 7);
        bs[tid] = bih[R] + bhh[R];
    }
    __syncthreads();

    float cst = 0.f;
    for (int t = 0; t < SQ; ++t) {
        const __nv_bfloat16* gh = g_h1h + (size_t)(t * 2 + bh) * HBH;
        const __nv_bfloat16* gl = g_h1l + (size_t)(t * 2 + bh) * HBH;
        stageC(SB0u, gh, gl, tid);               CP_COMMIT();
        stageC(SB1u, gh + 8192, gl + 8192, tid); CP_COMMIT();

        float d[4] = {0.f, 0.f, 0.f, 0.f};
        CP_WAIT1(); __syncthreads();
        mma_chunk(SB0u, WSu + bOff, d, aoff);
        CP_WAIT0(); __syncthreads();
        mma_chunk(SB1u, WSu + 16384u + bOff, d, aoff);

        gp[dr * GPLD + dc]           = d[0];
        gp[(dr + 1) * GPLD + dc]     = d[1];
        gp[dr * GPLD + dc + 8]       = d[2];
        gp[(dr + 1) * GPLD + dc + 8] = d[3];
        __syncthreads();

        int p = g_pidx[t * 64 + bh * 32 + bl_e];
        float gv[4];
        #pragma unroll
        for (int gate = 0; gate < 4; ++gate) {
            int r = (gate << 3) + uu;
            gv[gate] = bs[r] + E2s[(p << 5) + r] + gp[r * GPLD + bl_e];
        }
        float ig = sigmoidf_(gv[0]);
        float fg = sigmoidf_(gv[1]);
        float gg = tanhf(gv[2]);
        float og = sigmoidf_(gv[3]);
        cst = fg * cst + ig * gg;
        float hv = og * tanhf(cst);
        {
            __nv_bfloat16 hi = __float2bfloat16(hv);
            float rem = hv - __bfloat162float(hi);
            __nv_bfloat16 lo = __float2bfloat16(rem);
            size_t off = (size_t)((t + 1) * 2 + bh) * HBH + eoff_h((ug << 3) + uu, bl_e);
            stg_bf16(g_h1h + off, hi);
            stg_bf16(g_h1l + off, lo);
        }
        half_barrier(++gen, bh, grp);
    }

    // ======== layer 1 weights: K=1024 (Wih2 k<512 | Whh2 k>=512) ========
    {
        const float* Wih1 = Wih + (size_t)4 * H * H;
        const float* Whh1 = Whh + (size_t)4 * H * H;
        for (int idx = tid; idx < 32 * 2 * H; idx += NTHREADS) {
            int r = idx >> 10, k = idx & 1023;
            int R = ((r >> 3) << 9) + (ug << 3) + (r & 7);
            float w = (k < H) ? Wih1[(size_t)R * H + k] : Whh1[(size_t)R * H + (k - H)];
            __nv_bfloat16 hi = __float2bfloat16(w);
            float rem = w - __bfloat162float(hi);
            __nv_bfloat16 lo = __float2bfloat16(rem);
            int e = (k >> 1) * 64 + (k & 1) * 32 + ((((r >> 3) ^ ((k >> 1) & 3))) << 3) + (r & 7);
            wsh[e] = hi; wsl[e] = lo;
        }
        if (tid < 32) {
            int R = ((tid >> 3) << 9) + (ug << 3) + (tid & 7);
            bs[tid] = bih[2048 + R] + bhh[2048 + R];
        }
        __syncthreads();
    }

    // prefetch x chunks for t=0 (x = h1 snapshot 1; already materialized)
    {
        const __nv_bfloat16* xh = g_h1h + (size_t)(1 * 2 + bh) * HBH;
        const __nv_bfloat16* xl = g_h1l + (size_t)(1 * 2 + bh) * HBH;
        stageC(SB0u, xh, xl, tid);               CP_COMMIT();
        stageC(SB1u, xh + 8192, xl + 8192, tid); CP_COMMIT();
    }

    cst = 0.f;
    for (int t = 0; t < SQ; ++t) {
        const __nv_bfloat16* h2h = g_h2h + (size_t)((t & 1) * 2 + bh) * HBH;
        const __nv_bfloat16* h2l = g_h2l + (size_t)((t & 1) * 2 + bh) * HBH;

        float d[4] = {0.f, 0.f, 0.f, 0.f};
        // x chunk 0 (prefetched across barrier)
        CP_WAIT1(); __syncthreads();
        mma_chunk(SB0u, WSu + bOff, d, aoff);
        __syncthreads();
        stageC(SB0u, h2h, h2l, tid); CP_COMMIT();               // h2 chunk 0
        // x chunk 1
        CP_WAIT1(); __syncthreads();
        mma_chunk(SB1u, WSu + 16384u + bOff, d, aoff);
        __syncthreads();
        stageC(SB1u, h2h + 8192, h2l + 8192, tid); CP_COMMIT(); // h2 chunk 1
        // h2 chunk 0
        CP_WAIT1(); __syncthreads();
        mma_chunk(SB0u, WSu + 32768u + bOff, d, aoff);
        // h2 chunk 1
        CP_WAIT0(); __syncthreads();
        mma_chunk(SB1u, WSu + 49152u + bOff, d, aoff);

        gp[dr * GPLD + dc]           = d[0];
        gp[(dr + 1) * GPLD + dc]     = d[1];
        gp[dr * GPLD + dc + 8]       = d[2];
        gp[(dr + 1) * GPLD + dc + 8] = d[3];
        __syncthreads();

        float gv[4];
        #pragma unroll
        for (int gate = 0; gate < 4; ++gate) {
            int r = (gate << 3) + uu;
            gv[gate] = bs[r] + gp[r * GPLD + bl_e];
        }
        float ig = sigmoidf_(gv[0]);
        float fg = sigmoidf_(gv[1]);
        float gg = tanhf(gv[2]);
        float og = sigmoidf_(gv[3]);
        cst = fg * cst + ig * gg;
        float hv = og * tanhf(cst);
        {
            __nv_bfloat16 hi = __float2bfloat16(hv);
            float rem = hv - __bfloat162float(hi);
            __nv_bfloat16 lo = __float2bfloat16(rem);
            size_t off = (size_t)(((t + 1) & 1) * 2 + bh) * HBH + eoff_h((ug << 3) + uu, bl_e);
            stg_bf16(g_h2h + off, hi);
            stg_bf16(g_h2l + off, lo);
        }

        if (t + 1 < SQ) {   // prefetch next x; DMA overlaps the barrier wait
            const __nv_bfloat16* xh = g_h1h + (size_t)((t + 2) * 2 + bh) * HBH;
            const __nv_bfloat16* xl = g_h1l + (size_t)((t + 2) * 2 + bh) * HBH;
            stageC(SB0u, xh, xl, tid);               CP_COMMIT();
            stageC(SB1u, xh + 8192, xl + 8192, tid); CP_COMMIT();
        }
        half_barrier(++gen, bh, grp);
    }

    // ======== head: LayerNorm + projection (final h2 in slot 0) ========
    if (cta < 8) {
        int half = cta & 1;
        int bl = ((cta >> 1) << 3) + warp;    // 0..31 within half
        const __nv_bfloat16* h2h = g_h2h + (size_t)half * HBH;
        const __nv_bfloat16* h2l = g_h2l + (size_t)half * HBH;
        float s1 = 0.f, s2 = 0.f;
        for (int u = lane; u < H; u += 32) {
            int off = eoff_h(u, bl);
            float v = ldg_bf16(h2h + off) + ldg_bf16(h2l + off);
            s1 += v; s2 += v * v;
        }
        #pragma unroll
        for (int o = 16; o; o >>= 1) {
            s1 += __shfl_xor_sync(0xFFFFFFFFu, s1, o);
            s2 += __shfl_xor_sync(0xFFFFFFFFu, s2, o);
        }
        float mu  = s1 * (1.f / H);
        float var = s2 * (1.f / H) - mu * mu;
        float rs  = rsqrtf(var + 1e-5f);
        float acc = 0.f;
        for (int u = lane; u < H; u += 32) {
            int off = eoff_h(u, bl);
            float v  = ldg_bf16(h2h + off) + ldg_bf16(h2l + off);
            float hn = (v - mu) * rs * ln_g[u] + ln_b[u];
            acc += hn * Wp[u];
        }
        #pragma unroll
        for (int o = 16; o; o >>= 1) acc += __shfl_xor_sync(0xFFFFFFFFu, acc, o);
        if (lane == 0) out[half * 32 + bl] = acc + bp[0];
    }
}

// ---------------- launch ----------------
extern "C" void kernel_launch(void* const* d_in, const int* in_sizes, int n_in,
                              void* d_out, int out_size) {
    const void*  inp   = d_in[0];
    const float* embed = (const float*)d_in[1];
    const float* Wih   = (const float*)d_in[2];
    const float* Whh   = (const float*)d_in[3];
    const float* bih   = (const float*)d_in[4];
    const float* bhh   = (const float*)d_in[5];
    const float* ln_g  = (const float*)d_in[6];
    const float* ln_b  = (const float*)d_in[7];
    const float* Wp    = (const float*)d_in[8];
    const float* bp    = (const float*)d_in[9];
    float* out = (float*)d_out;

    detect_reset<<<1, 1>>>();
    detect_dtype<<<512, 256>>>((const unsigned*)inp);
    setup_misc<<<512, 256>>>(inp);
    setup_e2<<<128, 256>>>(embed, Wih);

    cudaFuncSetAttribute(lstm_persist, cudaFuncAttributeMaxDynamicSharedMemorySize, SMEM_TOT);
    lstm_persist<<<GRID, NTHREADS, SMEM_TOT>>>(Wih, Whh, bih, bhh, ln_g, ln_b, Wp, bp, out);
}

// round 7
// speedup vs baseline: 2.4773x; 1.2731x over previous
#include <cuda_runtime.h>
#include <cuda_bf16.h>
#include <cstdint>

// ---------------- problem constants ----------------
#define GRID     128
#define NTHREADS 256
#define SQ       2048
#define H        512
#define HBH      16384     // elements per (t, half) plane: 512 units x 32 batches
#define GPLD     34

// smem byte offsets
#define SMEM_SB   0        // 3 staging buffers x 8KB (hi 4KB | lo 4KB each)
#define SMEM_W1   24576    // layer1 Whh: hi 32KB | lo 32KB
#define SMEM_W2   90112    // layer2 (Wih2|Whh2): hi 64KB | lo 64KB
#define SMEM_GPA  221184   // 32 x GPLD x f32 (layer1 gates)
#define SMEM_GPB  225536   // 32 x GPLD x f32 (layer2 gates)
#define SMEM_E2S  229888   // 16 pairs x 32 rows f32
#define SMEM_BS   231936   // 64 f32 (L1 bias 0..31 | L2 bias 32..63)
#define SMEM_TOT  232192

// ---------------- device scratch ----------------
__device__ __align__(16) __nv_bfloat16 g_h1h[(SQ + 1) * 2 * HBH];
__device__ __align__(16) __nv_bfloat16 g_h1l[(SQ + 1) * 2 * HBH];
__device__ __align__(16) __nv_bfloat16 g_h2h[2 * 2 * HBH];
__device__ __align__(16) __nv_bfloat16 g_h2l[2 * 2 * HBH];
__device__ __align__(16) float g_E2[16 * 4 * H];
__device__ int      g_pidx[SQ * 64];
__device__ unsigned g_isI32;
__device__ unsigned g_c1[2 * 8 * 32];
__device__ unsigned g_c2[2 * 32];
__device__ unsigned g_gen[2 * 32];

__device__ __forceinline__ float sigmoidf_(float x) { return 1.f / (1.f + expf(-x)); }

// element offset inside one (t, half) plane: paired-k 128B rows, XOR swizzle
__device__ __forceinline__ int eoff_h(int k, int b) {
    return (k >> 1) * 64 + (k & 1) * 32 + ((((b >> 3) ^ ((k >> 1) & 3))) << 3) + (b & 7);
}

// ---------------- PTX helpers ----------------
__device__ __forceinline__ void ldmx4t(unsigned* r, uint32_t a) {
    asm volatile("ldmatrix.sync.aligned.m8n8.x4.trans.shared.b16 {%0,%1,%2,%3},[%4];"
                 : "=r"(r[0]), "=r"(r[1]), "=r"(r[2]), "=r"(r[3]) : "r"(a));
}
__device__ __forceinline__ void ldmx2t(unsigned* r, uint32_t a) {
    asm volatile("ldmatrix.sync.aligned.m8n8.x2.trans.shared.b16 {%0,%1},[%2];"
                 : "=r"(r[0]), "=r"(r[1]) : "r"(a));
}
__device__ __forceinline__ void mma16816(float* d, const unsigned* a, const unsigned* b) {
    asm volatile("mma.sync.aligned.m16n8k16.row.col.f32.bf16.bf16.f32 "
                 "{%0,%1,%2,%3},{%4,%5,%6,%7},{%8,%9},{%0,%1,%2,%3};"
                 : "+f"(d[0]), "+f"(d[1]), "+f"(d[2]), "+f"(d[3])
                 : "r"(a[0]), "r"(a[1]), "r"(a[2]), "r"(a[3]), "r"(b[0]), "r"(b[1]));
}
__device__ __forceinline__ void stg_bf16(__nv_bfloat16* p, __nv_bfloat16 v) {
    unsigned short u = *reinterpret_cast<unsigned short*>(&v);
    asm volatile("st.global.cg.u16 [%0], %1;" :: "l"(p), "h"(u) : "memory");
}
__device__ __forceinline__ float ldg_bf16(const __nv_bfloat16* p) {
    unsigned short u;
    asm volatile("ld.global.cg.u16 %0,[%1];" : "=h"(u) : "l"(p));
    __nv_bfloat16 b = *reinterpret_cast<__nv_bfloat16*>(&u);
    return __bfloat162float(b);
}

// Hierarchical per-half barrier (proven R6). Replay-safe.
__device__ __forceinline__ void half_barrier(unsigned target, int half, int grp) {
    __syncthreads();
    if (threadIdx.x == 0) {
        unsigned* c1 = &g_c1[(half * 8 + grp) * 32];
        unsigned* c2 = &g_c2[half * 32];
        unsigned* gv = &g_gen[half * 32];
        unsigned p1;
        asm volatile("atom.acq_rel.gpu.global.add.u32 %0,[%1],%2;"
                     : "=r"(p1) : "l"(c1), "r"(1u) : "memory");
        bool done = false;
        if (p1 == 7u) {
            asm volatile("st.relaxed.gpu.global.u32 [%0],%1;" :: "l"(c1), "r"(0u) : "memory");
            unsigned p2;
            asm volatile("atom.acq_rel.gpu.global.add.u32 %0,[%1],%2;"
                         : "=r"(p2) : "l"(c2), "r"(1u) : "memory");
            if (p2 == 7u) {
                asm volatile("st.relaxed.gpu.global.u32 [%0],%1;" :: "l"(c2), "r"(0u) : "memory");
                asm volatile("st.release.gpu.global.u32 [%0],%1;" :: "l"(gv), "r"(target) : "memory");
                done = true;
            }
        }
        if (!done) {
            unsigned cur;
            do {
                asm volatile("ld.acquire.gpu.global.u32 %0,[%1];" : "=r"(cur) : "l"(gv) : "memory");
            } while ((int)(cur - target) < 0);
        }
    }
    __syncthreads();
}

// stage one 8KB chunk (hi 4KB + lo 4KB); 2 cp.async per thread
__device__ __forceinline__ void stage8(uint32_t sb, const __nv_bfloat16* gh,
                                       const __nv_bfloat16* gl, int tid) {
    uint32_t s = sb + (uint32_t)tid * 16u;
    asm volatile("cp.async.cg.shared.global [%0],[%1],16;"
                 :: "r"(s), "l"((const char*)gh + tid * 16) : "memory");
    asm volatile("cp.async.cg.shared.global [%0],[%1],16;"
                 :: "r"(s + 4096u), "l"((const char*)gl + tid * 16) : "memory");
}
#define CP_COMMIT() asm volatile("cp.async.commit_group;" ::: "memory")
#define CP_WAIT2()  asm volatile("cp.async.wait_group 2;" ::: "memory")
#define CP_WAIT1()  asm volatile("cp.async.wait_group 1;" ::: "memory")
#define CP_WAIT0()  asm volatile("cp.async.wait_group 0;" ::: "memory")

// ---------------- setup kernels ----------------
__global__ void detect_reset() { g_isI32 = 0u; }

// int64 values in [0,4) -> odd u32 words all zero; int32 -> some nonzero.
__global__ void detect_dtype(const unsigned* __restrict__ w) {
    int i = blockIdx.x * blockDim.x + threadIdx.x;
    if (i < SQ * 64) {
        if ((i & 1) && w[i] != 0u) atomicOr(&g_isI32, 1u);
    }
}

__global__ void setup_misc(const void* __restrict__ inp_raw) {
    int i = blockIdx.x * blockDim.x + threadIdx.x;
    if (i < SQ * 64) {
        int s = i >> 6, b = i & 63;
        long long a, c;
        if (g_isI32) {
            const int* p = (const int*)inp_raw;
            a = p[b * SQ + s];
            c = p[(64 + b) * SQ + s];
        } else {
            const long long* p = (const long long*)inp_raw;
            a = p[(long long)b * SQ + s];
            c = p[(long long)(64 + b) * SQ + s];
        }
        g_pidx[s * 64 + b] = (int)(a * 4 + c);
    }
    __nv_bfloat16 z = __float2bfloat16(0.f);
    if (i < 2 * HBH) { g_h1h[i] = z; g_h1l[i] = z; }
    if (i < 4 * HBH) { g_h2h[i] = z; g_h2l[i] = z; }
}

__global__ void setup_e2(const float* __restrict__ embed, const float* __restrict__ Wih) {
    int flat = blockIdx.x * blockDim.x + threadIdx.x;
    int p = flat >> 11, r = flat & 2047;
    const float* e0 = embed + (p >> 2) * H;
    const float* e1 = embed + (p & 3) * H;
    const float* w  = Wih + (size_t)r * H;
    float s = 0.f;
    #pragma unroll 4
    for (int k = 0; k < H; k++) s += (e0[k] + e1[k]) * w[k];
    g_E2[p * 2048 + r] = s;
}

// ---------------- persistent merged-layer LSTM kernel ----------------
// CTA = (ug = cta>>1 unit-group 0..63, bh = cta&1 batch half). Owns 8 units of
// BOTH layers. Interval i: layer1[t=i] (i<SQ) and layer2[t=i-1] (i>0); both
// share the staged h1 slot-i chunks. One barrier per interval.
__global__ __launch_bounds__(NTHREADS, 1)
void lstm_persist(const float* __restrict__ Wih, const float* __restrict__ Whh,
                  const float* __restrict__ bih, const float* __restrict__ bhh,
                  const float* __restrict__ ln_g, const float* __restrict__ ln_b,
                  const float* __restrict__ Wp,  const float* __restrict__ bp,
                  float* __restrict__ out)
{
    extern __shared__ char smem[];
    __nv_bfloat16* w1h = (__nv_bfloat16*)(smem + SMEM_W1);
    __nv_bfloat16* w1l = (__nv_bfloat16*)(smem + SMEM_W1 + 32768);
    __nv_bfloat16* w2h = (__nv_bfloat16*)(smem + SMEM_W2);
    __nv_bfloat16* w2l = (__nv_bfloat16*)(smem + SMEM_W2 + 65536);
    float* gpA = (float*)(smem + SMEM_GPA);
    float* gpB = (float*)(smem + SMEM_GPB);
    float* E2s = (float*)(smem + SMEM_E2S);
    float* bs  = (float*)(smem + SMEM_BS);
    uint32_t su = (uint32_t)__cvta_generic_to_shared(smem);
    const uint32_t SBu = su + SMEM_SB, W1u = su + SMEM_W1, W2u = su + SMEM_W2;
    __shared__ unsigned s_base;

    const int cta  = blockIdx.x;
    const int tid  = threadIdx.x;
    const int warp = tid >> 5, lane = tid & 31;
    const int ug   = cta >> 1;
    const int bh   = cta & 1;
    const int grp  = ug >> 3;
    const int rn = warp >> 1;      // row n8-tile 0..3
    const int bm = warp & 1;       // batch m16-tile 0..1
    const int uu = tid >> 5, bl_e = tid & 31;

    // ldmatrix per-lane offsets (proven R6 formulas)
    const int kA  = (lane & 7) + ((lane & 16) >> 1);
    const int jbA = bm * 2 + ((lane >> 3) & 1);
    const uint32_t aoff = (uint32_t)((kA >> 1) * 128 + (kA & 1) * 64 +
                                     ((jbA ^ ((kA >> 1) & 3)) << 4));
    const int kB  = lane & 15;
    const uint32_t bOff = (uint32_t)((kB >> 1) * 128 + (kB & 1) * 64 +
                                     ((rn ^ ((kB >> 1) & 3)) << 4));
    const int dr = rn * 8 + ((lane & 3) << 1);
    const int dc = bm * 16 + (lane >> 2);

    if (tid == 0) {
        unsigned b_;
        asm volatile("ld.relaxed.gpu.global.u32 %0,[%1];" : "=r"(b_) : "l"(&g_gen[bh * 32]) : "memory");
        s_base = b_;
    }
    __syncthreads();
    unsigned gen = s_base;

    // ======== weight conversion: W1 (Whh layer0), W2 (Wih1|Whh1) ========
    for (int idx = tid; idx < 32 * H; idx += NTHREADS) {
        int r = idx >> 9, k = idx & (H - 1);
        int R = ((r >> 3) << 9) + (ug << 3) + (r & 7);
        float w = Whh[(size_t)R * H + k];
        __nv_bfloat16 hi = __float2bfloat16(w);
        __nv_bfloat16 lo = __float2bfloat16(w - __bfloat162float(hi));
        int e = (k >> 1) * 64 + (k & 1) * 32 + ((((r >> 3) ^ ((k >> 1) & 3))) << 3) + (r & 7);
        w1h[e] = hi; w1l[e] = lo;
    }
    {
        const float* Wih1 = Wih + (size_t)4 * H * H;
        const float* Whh1 = Whh + (size_t)4 * H * H;
        for (int idx = tid; idx < 32 * 2 * H; idx += NTHREADS) {
            int r = idx >> 10, k = idx & 1023;
            int R = ((r >> 3) << 9) + (ug << 3) + (r & 7);
            float w = (k < H) ? Wih1[(size_t)R * H + k] : Whh1[(size_t)R * H + (k - H)];
            __nv_bfloat16 hi = __float2bfloat16(w);
            __nv_bfloat16 lo = __float2bfloat16(w - __bfloat162float(hi));
            int e = (k >> 1) * 64 + (k & 1) * 32 + ((((r >> 3) ^ ((k >> 1) & 3))) << 3) + (r & 7);
            w2h[e] = hi; w2l[e] = lo;
        }
    }
    for (int idx = tid; idx < 512; idx += NTHREADS) {
        int p = idx >> 5, r = idx & 31;
        int R = ((r >> 3) << 9) + (ug << 3) + (r & 7);
        E2s[idx] = g_E2[p * 2048 + R];
    }
    if (tid < 32) {
        int R = ((tid >> 3) << 9) + (ug << 3) + (tid & 7);
        bs[tid]      = bih[R] + bhh[R];
        bs[tid + 32] = bih[2048 + R] + bhh[2048 + R];
    }
    __syncthreads();

    float cst1 = 0.f, cst2 = 0.f;

    for (int i = 0; i <= SQ; ++i) {
        const bool doL1 = (i < SQ);
        const bool doL2 = (i > 0);
        const int  nch  = doL2 ? 16 : 8;
        const size_t base1 = (size_t)(i * 2 + bh) * HBH;
        const size_t base2 = (size_t)((((i - 1) & 1)) * 2 + bh) * HBH;

        // issue first 3 chunks
        #pragma unroll
        for (int n = 0; n < 3; ++n) {
            const __nv_bfloat16 *gh, *gl;
            if (n < 8) { gh = g_h1h + base1 + n * 2048; gl = g_h1l + base1 + n * 2048; }
            else       { gh = g_h2h + base2 + (n - 8) * 2048; gl = g_h2l + base2 + (n - 8) * 2048; }
            stage8(SBu + (n % 3) * 8192u, gh, gl, tid);
            CP_COMMIT();
        }

        float d1hh[4] = {0,0,0,0}, d1hl[4] = {0,0,0,0}, d1lh[4] = {0,0,0,0};
        float d2hh[4] = {0,0,0,0}, d2hl[4] = {0,0,0,0}, d2lh[4] = {0,0,0,0};

        for (int c = 0; c < nch; ++c) {
            int rem = nch - 1 - c;
            if (rem >= 2)      { CP_WAIT2(); }
            else if (rem == 1) { CP_WAIT1(); }
            else               { CP_WAIT0(); }
            __syncthreads();

            uint32_t ab  = SBu + (uint32_t)(c % 3) * 8192u + aoff;
            uint32_t b1  = W1u + (uint32_t)c * 4096u + bOff;
            uint32_t b2  = W2u + (uint32_t)c * 4096u + bOff;
            const bool l1 = (c < 8) && doL1;
            #pragma unroll
            for (int t = 0; t < 4; ++t) {
                unsigned Ah[4], Al[4], B1h[2], B1l[2], B2h[2], B2l[2];
                ldmx4t(Ah, ab);
                ldmx4t(Al, ab + 4096u);
                if (l1) {
                    ldmx2t(B1h, b1);
                    ldmx2t(B1l, b1 + 32768u);
                    mma16816(d1hh, Ah, B1h);
                    mma16816(d1hl, Ah, B1l);
                    mma16816(d1lh, Al, B1h);
                }
                if (doL2) {
                    ldmx2t(B2h, b2);
                    ldmx2t(B2l, b2 + 65536u);
                    mma16816(d2hh, Ah, B2h);
                    mma16816(d2hl, Ah, B2l);
                    mma16816(d2lh, Al, B2h);
                }
                ab += 1024u; b1 += 1024u; b2 += 1024u;
            }
            __syncthreads();

            int n = c + 3;
            if (n < nch) {
                const __nv_bfloat16 *gh, *gl;
                if (n < 8) { gh = g_h1h + base1 + n * 2048; gl = g_h1l + base1 + n * 2048; }
                else       { gh = g_h2h + base2 + (n - 8) * 2048; gl = g_h2l + base2 + (n - 8) * 2048; }
                stage8(SBu + (uint32_t)(n % 3) * 8192u, gh, gl, tid);
                CP_COMMIT();
            }
        }

        // write gate partials
        if (doL1) {
            gpA[dr * GPLD + dc]           = d1hh[0] + d1hl[0] + d1lh[0];
            gpA[(dr + 1) * GPLD + dc]     = d1hh[1] + d1hl[1] + d1lh[1];
            gpA[dr * GPLD + dc + 8]       = d1hh[2] + d1hl[2] + d1lh[2];
            gpA[(dr + 1) * GPLD + dc + 8] = d1hh[3] + d1hl[3] + d1lh[3];
        }
        if (doL2) {
            gpB[dr * GPLD + dc]           = d2hh[0] + d2hl[0] + d2lh[0];
            gpB[(dr + 1) * GPLD + dc]     = d2hh[1] + d2hl[1] + d2lh[1];
            gpB[dr * GPLD + dc + 8]       = d2hh[2] + d2hl[2] + d2lh[2];
            gpB[(dr + 1) * GPLD + dc + 8] = d2hh[3] + d2hl[3] + d2lh[3];
        }
        __syncthreads();

        // eltwise layer1
        if (doL1) {
            int p = g_pidx[i * 64 + bh * 32 + bl_e];
            float gv[4];
            #pragma unroll
            for (int gate = 0; gate < 4; ++gate) {
                int r = (gate << 3) + uu;
                gv[gate] = bs[r] + E2s[(p << 5) + r] + gpA[r * GPLD + bl_e];
            }
            float ig = sigmoidf_(gv[0]);
            float fg = sigmoidf_(gv[1]);
            float gg = tanhf(gv[2]);
            float og = sigmoidf_(gv[3]);
            cst1 = fg * cst1 + ig * gg;
            float hv = og * tanhf(cst1);
            __nv_bfloat16 hi = __float2bfloat16(hv);
            __nv_bfloat16 lo = __float2bfloat16(hv - __bfloat162float(hi));
            size_t off = (size_t)((i + 1) * 2 + bh) * HBH + eoff_h((ug << 3) + uu, bl_e);
            stg_bf16(g_h1h + off, hi);
            stg_bf16(g_h1l + off, lo);
        }
        // eltwise layer2
        if (doL2) {
            float gv[4];
            #pragma unroll
            for (int gate = 0; gate < 4; ++gate) {
                int r = (gate << 3) + uu;
                gv[gate] = bs[32 + r] + gpB[r * GPLD + bl_e];
            }
            float ig = sigmoidf_(gv[0]);
            float fg = sigmoidf_(gv[1]);
            float gg = tanhf(gv[2]);
            float og = sigmoidf_(gv[3]);
            cst2 = fg * cst2 + ig * gg;
            float hv = og * tanhf(cst2);
            __nv_bfloat16 hi = __float2bfloat16(hv);
            __nv_bfloat16 lo = __float2bfloat16(hv - __bfloat162float(hi));
            size_t off = (size_t)((i & 1) * 2 + bh) * HBH + eoff_h((ug << 3) + uu, bl_e);
            stg_bf16(g_h2h + off, hi);
            stg_bf16(g_h2l + off, lo);
        }
        half_barrier(++gen, bh, grp);
    }

    // ======== head: LayerNorm + projection (final h2 at parity 0) ========
    if (cta < 8) {
        int half = cta & 1;
        int bl = ((cta >> 1) << 3) + warp;
        const __nv_bfloat16* h2h = g_h2h + (size_t)half * HBH;
        const __nv_bfloat16* h2l = g_h2l + (size_t)half * HBH;
        float s1 = 0.f, s2 = 0.f;
        for (int u = lane; u < H; u += 32) {
            int off = eoff_h(u, bl);
            float v = ldg_bf16(h2h + off) + ldg_bf16(h2l + off);
            s1 += v; s2 += v * v;
        }
        #pragma unroll
        for (int o = 16; o; o >>= 1) {
            s1 += __shfl_xor_sync(0xFFFFFFFFu, s1, o);
            s2 += __shfl_xor_sync(0xFFFFFFFFu, s2, o);
        }
        float mu  = s1 * (1.f / H);
        float var = s2 * (1.f / H) - mu * mu;
        float rs  = rsqrtf(var + 1e-5f);
        float acc = 0.f;
        for (int u = lane; u < H; u += 32) {
            int off = eoff_h(u, bl);
            float v  = ldg_bf16(h2h + off) + ldg_bf16(h2l + off);
            float hn = (v - mu) * rs * ln_g[u] + ln_b[u];
            acc += hn * Wp[u];
        }
        #pragma unroll
        for (int o = 16; o; o >>= 1) acc += __shfl_xor_sync(0xFFFFFFFFu, acc, o);
        if (lane == 0) out[half * 32 + bl] = acc + bp[0];
    }
}

// ---------------- launch ----------------
extern "C" void kernel_launch(void* const* d_in, const int* in_sizes, int n_in,
                              void* d_out, int out_size) {
    const void*  inp   = d_in[0];
    const float* embed = (const float*)d_in[1];
    const float* Wih   = (const float*)d_in[2];
    const float* Whh   = (const float*)d_in[3];
    const float* bih   = (const float*)d_in[4];
    const float* bhh   = (const float*)d_in[5];
    const float* ln_g  = (const float*)d_in[6];
    const float* ln_b  = (const float*)d_in[7];
    const float* Wp    = (const float*)d_in[8];
    const float* bp    = (const float*)d_in[9];
    float* out = (float*)d_out;

    detect_reset<<<1, 1>>>();
    detect_dtype<<<512, 256>>>((const unsigned*)inp);
    setup_misc<<<512, 256>>>(inp);
    setup_e2<<<128, 256>>>(embed, Wih);

    cudaFuncSetAttribute(lstm_persist, cudaFuncAttributeMaxDynamicSharedMemorySize, SMEM_TOT);
    lstm_persist<<<GRID, NTHREADS, SMEM_TOT>>>(Wih, Whh, bih, bhh, ln_g, ln_b, Wp, bp, out);
}